// round 1
// baseline (speedup 1.0000x reference)
#include <cuda_runtime.h>
#include <mma.h>
#include <math.h>

using namespace nvcuda;

// Problem dims (fixed)
constexpr int Bn = 16;
constexpr int Ln = 4096;
constexpr int Dn = 512;
constexpr int Hn = 512;
constexpr int M_ROWS = Bn * Ln;      // 65536
constexpr int NC = 16;               // scan chunks per sequence
constexpr int CL = Ln / NC;          // 256 timesteps per chunk
constexpr int BH = Bn * Hn;          // 8192 channels

// ------------------------- scratch (static device globals) ------------------
__device__ float g_u  [(size_t)M_ROWS * 3 * Hn];   // 402 MB : SRU projections (z|f|r)
__device__ float g_y  [(size_t)M_ROWS * Dn];       // 134 MB : post-SRU / pre-LN2 (reused)
__device__ float g_xln[(size_t)M_ROWS * Dn];       // 134 MB : LN1 output (residual source)
__device__ float g_h  [(size_t)M_ROWS * 4 * Dn];   // 536 MB : GELU(MLP hidden)
__device__ float g_P  [BH * NC];
__device__ float g_A  [BH * NC];
__device__ float g_cs [BH * NC];

__device__ __forceinline__ float sigmoidf_(float t) {
    return 1.0f / (1.0f + __expf(-t));
}

__device__ __forceinline__ float gelu_erf(float v) {
    return 0.5f * v * (1.0f + erff(v * 0.70710678118654752440f));
}

// ------------------------- tf32 WMMA GEMM ----------------------------------
// C[M,N] = A[M,K] @ B[K,N]  (all row-major fp32; tf32 MMA, fp32 accumulate)
// EPI 0: plain store   EPI 1: gelu(x + bias[n])   EPI 2: x + bias[n] + res[m,n]
// Tiles: BM=128, BN=64, BK=16. 256 threads = 8 warps (4x2), warp tile 32x32.
template<int EPI>
__global__ void __launch_bounds__(256) gemm_tf32(
    const float* __restrict__ A, const float* __restrict__ B,
    const float* __restrict__ bias, const float* __restrict__ res,
    float* __restrict__ C, int M, int N, int K)
{
    __shared__ float sA[128][20];      // 128 x 16, pad 4
    __shared__ float sB[16][68];       // 16 x 64, pad 4
    __shared__ float stage[8][16][20]; // per-warp epilogue staging

    const int tid  = threadIdx.x;
    const int warp = tid >> 5;
    const int lane = tid & 31;
    const int m0 = blockIdx.y * 128;
    const int n0 = blockIdx.x * 64;
    const int wm = warp >> 1;          // 0..3
    const int wn = warp & 1;           // 0..1

    wmma::fragment<wmma::accumulator, 16, 16, 8, float> acc[2][2];
#pragma unroll
    for (int i = 0; i < 2; i++)
#pragma unroll
        for (int j = 0; j < 2; j++) wmma::fill_fragment(acc[i][j], 0.0f);

    const int ar  = tid >> 2;          // 0..63
    const int ac4 = (tid & 3) << 2;    // 0,4,8,12
    const int br  = tid >> 4;          // 0..15
    const int bc4 = (tid & 15) << 2;   // 0..60

    const float* Abase = A + (size_t)(m0 + ar) * K + ac4;
    const float* Bbase = B + (size_t)br * N + (n0 + bc4);

    for (int k0 = 0; k0 < K; k0 += 16) {
        float4 a0 = *reinterpret_cast<const float4*>(Abase + k0);
        float4 a1 = *reinterpret_cast<const float4*>(Abase + (size_t)64 * K + k0);
        float4 b0 = *reinterpret_cast<const float4*>(Bbase + (size_t)k0 * N);
        *reinterpret_cast<float4*>(&sA[ar][ac4])      = a0;
        *reinterpret_cast<float4*>(&sA[ar + 64][ac4]) = a1;
        *reinterpret_cast<float4*>(&sB[br][bc4])      = b0;
        __syncthreads();

#pragma unroll
        for (int kk = 0; kk < 16; kk += 8) {
            wmma::fragment<wmma::matrix_a, 16, 16, 8, wmma::precision::tf32, wmma::row_major> af[2];
            wmma::fragment<wmma::matrix_b, 16, 16, 8, wmma::precision::tf32, wmma::row_major> bf[2];
#pragma unroll
            for (int i = 0; i < 2; i++) {
                wmma::load_matrix_sync(af[i], &sA[wm * 32 + i * 16][kk], 20);
#pragma unroll
                for (int t = 0; t < af[i].num_elements; t++)
                    af[i].x[t] = wmma::__float_to_tf32(af[i].x[t]);
            }
#pragma unroll
            for (int j = 0; j < 2; j++) {
                wmma::load_matrix_sync(bf[j], &sB[kk][wn * 32 + j * 16], 68);
#pragma unroll
                for (int t = 0; t < bf[j].num_elements; t++)
                    bf[j].x[t] = wmma::__float_to_tf32(bf[j].x[t]);
            }
#pragma unroll
            for (int i = 0; i < 2; i++)
#pragma unroll
                for (int j = 0; j < 2; j++)
                    wmma::mma_sync(acc[i][j], af[i], bf[j], acc[i][j]);
        }
        __syncthreads();
    }

    if (EPI == 0) {
#pragma unroll
        for (int i = 0; i < 2; i++)
#pragma unroll
            for (int j = 0; j < 2; j++) {
                float* Cp = C + (size_t)(m0 + wm * 32 + i * 16) * N + (n0 + wn * 32 + j * 16);
                wmma::store_matrix_sync(Cp, acc[i][j], N, wmma::mem_row_major);
            }
    } else {
#pragma unroll
        for (int i = 0; i < 2; i++)
#pragma unroll
            for (int j = 0; j < 2; j++) {
                wmma::store_matrix_sync(&stage[warp][0][0], acc[i][j], 20, wmma::mem_row_major);
                __syncwarp();
#pragma unroll
                for (int e = 0; e < 8; e++) {
                    int idx = lane + e * 32;       // 0..255 over 16x16
                    int r = idx >> 4, cc = idx & 15;
                    int m = m0 + wm * 32 + i * 16 + r;
                    int n = n0 + wn * 32 + j * 16 + cc;
                    float v = stage[warp][r][cc];
                    if (EPI == 1) {
                        v += bias[n];
                        v = gelu_erf(v);
                    } else {
                        v += bias[n] + res[(size_t)m * N + n];
                    }
                    C[(size_t)m * N + n] = v;
                }
                __syncwarp();
            }
    }
}

// ------------------------- SRU chunked scan ---------------------------------
// u layout: [B, L, 3H] with cols [0,H)=z, [H,2H)=f_pre, [2H,3H)=r_pre
__global__ void __launch_bounds__(256) sru_passA(
    const float* __restrict__ u, const float* __restrict__ b_f,
    float* __restrict__ Pout, float* __restrict__ Aout)
{
    int idx = blockIdx.x * blockDim.x + threadIdx.x;   // BH*NC threads
    int h = idx % Hn;
    int j = (idx / Hn) % NC;
    int b = idx / (Hn * NC);
    float bf = b_f[h];
    const float* base = u + (size_t)b * Ln * 3 * Hn + h;
    float c = 0.0f, P = 1.0f;
    int t0 = j * CL;
#pragma unroll 4
    for (int t = t0; t < t0 + CL; ++t) {
        const float* p = base + (size_t)t * (3 * Hn);
        float z  = p[0];
        float fp = p[Hn];
        float f  = sigmoidf_(fp + bf);
        c = f * c + (1.0f - f) * z;
        P *= f;
    }
    int ch = b * Hn + h;
    Pout[ch * NC + j] = P;
    Aout[ch * NC + j] = c;
}

__global__ void __launch_bounds__(256) sru_combine(
    const float* __restrict__ P, const float* __restrict__ A,
    float* __restrict__ cstart)
{
    int ch = blockIdx.x * blockDim.x + threadIdx.x;    // BH threads
    float c = 0.0f;
#pragma unroll
    for (int j = 0; j < NC; j++) {
        cstart[ch * NC + j] = c;
        c = P[ch * NC + j] * c + A[ch * NC + j];
    }
}

__global__ void __launch_bounds__(256) sru_passC(
    const float* __restrict__ u, const float* __restrict__ x,
    const float* __restrict__ b_f, const float* __restrict__ b_r,
    const float* __restrict__ cstart, float* __restrict__ y)
{
    int idx = blockIdx.x * blockDim.x + threadIdx.x;
    int h = idx % Hn;
    int j = (idx / Hn) % NC;
    int b = idx / (Hn * NC);
    float bf = b_f[h];
    float br = b_r[h];
    int ch = b * Hn + h;
    float c = cstart[ch * NC + j];
    const float* ubase = u + (size_t)b * Ln * 3 * Hn + h;
    const float* xbase = x + (size_t)b * Ln * Dn + h;
    float* ybase = y + (size_t)b * Ln * Dn + h;
    int t0 = j * CL;
#pragma unroll 4
    for (int t = t0; t < t0 + CL; ++t) {
        const float* p = ubase + (size_t)t * (3 * Hn);
        float z  = p[0];
        float fp = p[Hn];
        float rp = p[2 * Hn];
        float f = sigmoidf_(fp + bf);
        c = f * c + (1.0f - f) * z;
        float r = sigmoidf_(rp + br);
        float xv = xbase[(size_t)t * Dn];
        // x_new = x + (r*c + (1-r)*x)
        ybase[(size_t)t * Dn] = xv + r * c + (1.0f - r) * xv;
    }
}

// ------------------------- LayerNorm (row of 512) ---------------------------
__global__ void __launch_bounds__(128) layernorm_k(
    const float* __restrict__ in, const float* __restrict__ g,
    const float* __restrict__ bb, float* __restrict__ out)
{
    __shared__ float red[4];
    int row = blockIdx.x;
    int tid = threadIdx.x;
    const float4* p = reinterpret_cast<const float4*>(in + (size_t)row * Dn);
    float4 v = p[tid];

    float s = v.x + v.y + v.z + v.w;
#pragma unroll
    for (int o = 16; o; o >>= 1) s += __shfl_xor_sync(0xffffffffu, s, o);
    if ((tid & 31) == 0) red[tid >> 5] = s;
    __syncthreads();
    float mean = (red[0] + red[1] + red[2] + red[3]) * (1.0f / 512.0f);

    float dx = v.x - mean, dy = v.y - mean, dz = v.z - mean, dw = v.w - mean;
    float ss = dx * dx + dy * dy + dz * dz + dw * dw;
#pragma unroll
    for (int o = 16; o; o >>= 1) ss += __shfl_xor_sync(0xffffffffu, ss, o);
    __syncthreads();
    if ((tid & 31) == 0) red[tid >> 5] = ss;
    __syncthreads();
    float var = (red[0] + red[1] + red[2] + red[3]) * (1.0f / 512.0f);
    float rstd = rsqrtf(var + 1e-5f);

    float4 gv = reinterpret_cast<const float4*>(g)[tid];
    float4 bv = reinterpret_cast<const float4*>(bb)[tid];
    float4 o4;
    o4.x = dx * rstd * gv.x + bv.x;
    o4.y = dy * rstd * gv.y + bv.y;
    o4.z = dz * rstd * gv.z + bv.z;
    o4.w = dw * rstd * gv.w + bv.w;
    reinterpret_cast<float4*>(out + (size_t)row * Dn)[tid] = o4;
}

// ------------------------- launch ------------------------------------------
extern "C" void kernel_launch(void* const* d_in, const int* in_sizes, int n_in,
                              void* d_out, int out_size)
{
    const float* x    = (const float*)d_in[0];
    const float* Wsru = (const float*)d_in[1];
    const float* b_f  = (const float*)d_in[2];
    const float* b_r  = (const float*)d_in[3];
    const float* ln1g = (const float*)d_in[4];
    const float* ln1b = (const float*)d_in[5];
    const float* W1   = (const float*)d_in[6];
    const float* b1   = (const float*)d_in[7];
    const float* W2   = (const float*)d_in[8];
    const float* b2   = (const float*)d_in[9];
    const float* ln2g = (const float*)d_in[10];
    const float* ln2b = (const float*)d_in[11];
    float* out = (float*)d_out;

    float *u, *y, *xln, *hb, *P, *A, *cs;
    cudaGetSymbolAddress((void**)&u,   g_u);
    cudaGetSymbolAddress((void**)&y,   g_y);
    cudaGetSymbolAddress((void**)&xln, g_xln);
    cudaGetSymbolAddress((void**)&hb,  g_h);
    cudaGetSymbolAddress((void**)&P,   g_P);
    cudaGetSymbolAddress((void**)&A,   g_A);
    cudaGetSymbolAddress((void**)&cs,  g_cs);

    // 1) u = x @ W_sru  (65536x512 @ 512x1536)
    gemm_tf32<0><<<dim3(3 * Hn / 64, M_ROWS / 128), 256>>>(
        x, Wsru, nullptr, nullptr, u, M_ROWS, 3 * Hn, Dn);

    // 2) SRU chunked scan + highway + residual  -> y
    sru_passA<<<BH * NC / 256, 256>>>(u, b_f, P, A);
    sru_combine<<<BH / 256, 256>>>(P, A, cs);
    sru_passC<<<BH * NC / 256, 256>>>(u, x, b_f, b_r, cs, y);

    // 3) LN1 -> xln
    layernorm_k<<<M_ROWS, 128>>>(y, ln1g, ln1b, xln);

    // 4) h = gelu(xln @ W1 + b1)  (65536x512 @ 512x2048)
    gemm_tf32<1><<<dim3(4 * Dn / 64, M_ROWS / 128), 256>>>(
        xln, W1, b1, nullptr, hb, M_ROWS, 4 * Dn, Dn);

    // 5) y = xln + h @ W2 + b2   (65536x2048 @ 2048x512)
    gemm_tf32<2><<<dim3(Dn / 64, M_ROWS / 128), 256>>>(
        hb, W2, b2, xln, y, M_ROWS, Dn, 4 * Dn);

    // 6) LN2 -> out
    layernorm_k<<<M_ROWS, 128>>>(y, ln2g, ln2b, out);
}

// round 3
// speedup vs baseline: 1.5907x; 1.5907x over previous
#include <cuda_runtime.h>
#include <math.h>
#include <cstdint>

// Problem dims (fixed)
constexpr int Bn = 16;
constexpr int Ln = 4096;
constexpr int Dn = 512;
constexpr int Hn = 512;
constexpr int M_ROWS = Bn * Ln;      // 65536
constexpr int NC = 32;               // scan chunks per sequence
constexpr int CL = Ln / NC;          // 128 timesteps per chunk
constexpr int BH = Bn * Hn;          // 8192 channels

// ------------------------- scratch (static device globals) ------------------
__device__ float g_u  [(size_t)M_ROWS * 3 * Hn];
__device__ float g_y  [(size_t)M_ROWS * Dn];
__device__ float g_xln[(size_t)M_ROWS * Dn];
__device__ float g_h  [(size_t)M_ROWS * 4 * Dn];
__device__ float g_P  [BH * NC];
__device__ float g_A  [BH * NC];
__device__ float g_cs [BH * NC];
__device__ float g_wsruT[3 * Hn * Dn];   // [1536,512]
__device__ float g_w1T  [4 * Dn * Dn];   // [2048,512]
__device__ float g_w2T  [Dn * 4 * Dn];   // [512,2048]

__device__ __forceinline__ float sigmoidf_(float t) {
    return 1.0f / (1.0f + __expf(-t));
}
__device__ __forceinline__ float gelu_erf(float v) {
    return 0.5f * v * (1.0f + erff(v * 0.70710678118654752440f));
}

__device__ __forceinline__ uint32_t s2u(const void* p) {
    uint32_t a;
    asm("{ .reg .u64 t; cvta.to.shared.u64 t, %1; cvt.u32.u64 %0, t; }" : "=r"(a) : "l"(p));
    return a;
}
__device__ __forceinline__ void cp16(uint32_t s, const void* g) {
    asm volatile("cp.async.cg.shared.global [%0], [%1], 16;" :: "r"(s), "l"(g));
}

// mma.sync tf32 m16n8k8 (fp32 bits passed through; HW uses tf32 subset)
__device__ __forceinline__ void mma8(float* d, const uint32_t* a, const uint32_t* b) {
    asm volatile(
        "mma.sync.aligned.m16n8k8.row.col.f32.tf32.tf32.f32 "
        "{%0,%1,%2,%3}, {%4,%5,%6,%7}, {%8,%9}, {%0,%1,%2,%3};"
        : "+f"(d[0]), "+f"(d[1]), "+f"(d[2]), "+f"(d[3])
        : "r"(a[0]), "r"(a[1]), "r"(a[2]), "r"(a[3]), "r"(b[0]), "r"(b[1]));
}

// ------------------------- tf32 mma.sync GEMM -------------------------------
// C[M,N] = A[M,K] @ Bt[N,K]^T. BM=BN=128, BK=16, NS=4 stage cp.async ring.
// 256 threads = 8 warps (2 m x 4 n), warp tile 64x32.
// Smem rows padded to 20 floats -> frag pattern 20*r+c conflict-free.
constexpr int BM = 128, BN = 128, BK = 16, NS = 4;
constexpr int ASF  = 128 * 20;           // floats per A (or B) stage
constexpr int STGF = 2 * ASF;            // floats per stage
constexpr int SMEM_GEMM = NS * STGF * 4; // 81920 bytes

__device__ __forceinline__ void load_stage(const float* __restrict__ A,
                                           const float* __restrict__ Bt,
                                           uint32_t sb, int m0, int n0, int K,
                                           int t, int tid) {
    const int buf = t & (NS - 1);
    const float* Ab = A  + (size_t)m0 * K + t * BK;
    const float* Bb = Bt + (size_t)n0 * K + t * BK;
    const uint32_t sA = sb + buf * (STGF * 4);
    const uint32_t sB = sA + ASF * 4;
#pragma unroll
    for (int i = 0; i < 2; i++) {
        int q   = tid + i * 256;   // 0..511
        int row = q >> 2;
        int j   = q & 3;
        uint32_t so = (uint32_t)(row * 20 + j * 4) * 4;
        cp16(sA + so, Ab + (size_t)row * K + j * 4);
        cp16(sB + so, Bb + (size_t)row * K + j * 4);
    }
    asm volatile("cp.async.commit_group;" ::: "memory");
}

// EPI 0: store   EPI 1: gelu(v + bias[n])   EPI 2: v + bias[n] + res[m,n]
template<int EPI>
__global__ void __launch_bounds__(256, 1) gemm_mma(
    const float* __restrict__ A, const float* __restrict__ Bt,
    const float* __restrict__ bias, const float* __restrict__ res,
    float* __restrict__ C, int N, int K)
{
    extern __shared__ float smemf[];
    const uint32_t sb = s2u(smemf);
    const int tid = threadIdx.x;
    const int w   = tid >> 5;
    const int lane = tid & 31;
    const int wm = w & 1;          // 0..1 (64 rows each)
    const int wn = w >> 1;         // 0..3 (32 cols each)
    const int gp = lane >> 2;      // 0..7
    const int tg = lane & 3;       // 0..3
    const int m0 = blockIdx.y * BM;
    const int n0 = blockIdx.x * BN;

    float acc[4][4][4];
#pragma unroll
    for (int i = 0; i < 4; i++)
#pragma unroll
        for (int j = 0; j < 4; j++)
#pragma unroll
            for (int e = 0; e < 4; e++) acc[i][j][e] = 0.0f;

    const int iters = K / BK;

    // prologue: stages 0..NS-2
#pragma unroll
    for (int s = 0; s < NS - 1; s++) load_stage(A, Bt, sb, m0, n0, K, s, tid);

    for (int s = 0; s < iters; s++) {
        const int pend = (iters - 1 - s) < (NS - 2) ? (iters - 1 - s) : (NS - 2);
        if      (pend >= 2) asm volatile("cp.async.wait_group 2;" ::: "memory");
        else if (pend == 1) asm volatile("cp.async.wait_group 1;" ::: "memory");
        else                asm volatile("cp.async.wait_group 0;" ::: "memory");
        __syncthreads();

        if (s + NS - 1 < iters) load_stage(A, Bt, sb, m0, n0, K, s + NS - 1, tid);

        const int buf = s & (NS - 1);
        const float* sA = smemf + buf * STGF;
        const float* sB = sA + ASF;
        const float* pa = sA + (wm * 64 + gp) * 20 + tg;
        const float* pb = sB + (wn * 32 + gp) * 20 + tg;

#pragma unroll
        for (int kk = 0; kk < 2; kk++) {
            const int kb = kk * 8;
            uint32_t af[4][4], bf[4][2];
#pragma unroll
            for (int mf = 0; mf < 4; mf++) {
                af[mf][0] = __float_as_uint(pa[mf * 320 + kb]);
                af[mf][1] = __float_as_uint(pa[mf * 320 + 160 + kb]);
                af[mf][2] = __float_as_uint(pa[mf * 320 + kb + 4]);
                af[mf][3] = __float_as_uint(pa[mf * 320 + 160 + kb + 4]);
            }
#pragma unroll
            for (int nf = 0; nf < 4; nf++) {
                bf[nf][0] = __float_as_uint(pb[nf * 160 + kb]);
                bf[nf][1] = __float_as_uint(pb[nf * 160 + kb + 4]);
            }
#pragma unroll
            for (int mf = 0; mf < 4; mf++)
#pragma unroll
                for (int nf = 0; nf < 4; nf++)
                    mma8(acc[mf][nf], af[mf], bf[nf]);
        }
    }

    // epilogue: register accs -> gmem (float2 stores)
#pragma unroll
    for (int mf = 0; mf < 4; mf++) {
        const int ma = m0 + wm * 64 + mf * 16 + gp;
        const int mb = ma + 8;
#pragma unroll
        for (int nf = 0; nf < 4; nf++) {
            const int n = n0 + wn * 32 + nf * 8 + 2 * tg;
            float2 v0 = make_float2(acc[mf][nf][0], acc[mf][nf][1]);
            float2 v1 = make_float2(acc[mf][nf][2], acc[mf][nf][3]);
            if (EPI == 1) {
                float b0 = bias[n], b1 = bias[n + 1];
                v0.x = gelu_erf(v0.x + b0); v0.y = gelu_erf(v0.y + b1);
                v1.x = gelu_erf(v1.x + b0); v1.y = gelu_erf(v1.y + b1);
            } else if (EPI == 2) {
                float b0 = bias[n], b1 = bias[n + 1];
                float2 r0 = *reinterpret_cast<const float2*>(res + (size_t)ma * N + n);
                float2 r1 = *reinterpret_cast<const float2*>(res + (size_t)mb * N + n);
                v0.x += b0 + r0.x; v0.y += b1 + r0.y;
                v1.x += b0 + r1.x; v1.y += b1 + r1.y;
            }
            *reinterpret_cast<float2*>(C + (size_t)ma * N + n) = v0;
            *reinterpret_cast<float2*>(C + (size_t)mb * N + n) = v1;
        }
    }
}

// ------------------------- weight transpose ---------------------------------
__global__ void __launch_bounds__(256) transpose_k(
    const float* __restrict__ in, float* __restrict__ out, int R, int C)
{
    __shared__ float t[32][33];
    int c0 = blockIdx.x * 32, r0 = blockIdx.y * 32;
    int x = threadIdx.x, y0 = threadIdx.y;
#pragma unroll
    for (int i = 0; i < 32; i += 8)
        t[y0 + i][x] = in[(size_t)(r0 + y0 + i) * C + c0 + x];
    __syncthreads();
#pragma unroll
    for (int i = 0; i < 32; i += 8)
        out[(size_t)(c0 + y0 + i) * R + r0 + x] = t[x][y0 + i];
}

// ------------------------- SRU chunked scan ---------------------------------
__global__ void __launch_bounds__(256) sru_passA(
    const float* __restrict__ u, const float* __restrict__ b_f,
    float* __restrict__ Pout, float* __restrict__ Aout)
{
    int idx = blockIdx.x * blockDim.x + threadIdx.x;   // BH*NC threads
    int h = idx % Hn;
    int j = (idx / Hn) % NC;
    int b = idx / (Hn * NC);
    float bf = b_f[h];
    const float* base = u + (size_t)b * Ln * 3 * Hn + h;
    float c = 0.0f, P = 1.0f;
    int t0 = j * CL;
#pragma unroll 4
    for (int t = t0; t < t0 + CL; ++t) {
        const float* p = base + (size_t)t * (3 * Hn);
        float z  = p[0];
        float fp = p[Hn];
        float f  = sigmoidf_(fp + bf);
        c = f * c + (1.0f - f) * z;
        P *= f;
    }
    int ch = b * Hn + h;
    Pout[ch * NC + j] = P;
    Aout[ch * NC + j] = c;
}

__global__ void __launch_bounds__(256) sru_combine(
    const float* __restrict__ P, const float* __restrict__ A,
    float* __restrict__ cstart)
{
    int ch = blockIdx.x * blockDim.x + threadIdx.x;    // BH threads
    float c = 0.0f;
#pragma unroll
    for (int j = 0; j < NC; j++) {
        cstart[ch * NC + j] = c;
        c = P[ch * NC + j] * c + A[ch * NC + j];
    }
}

__global__ void __launch_bounds__(256) sru_passC(
    const float* __restrict__ u, const float* __restrict__ x,
    const float* __restrict__ b_f, const float* __restrict__ b_r,
    const float* __restrict__ cstart, float* __restrict__ y)
{
    int idx = blockIdx.x * blockDim.x + threadIdx.x;
    int h = idx % Hn;
    int j = (idx / Hn) % NC;
    int b = idx / (Hn * NC);
    float bf = b_f[h];
    float br = b_r[h];
    int ch = b * Hn + h;
    float c = cstart[ch * NC + j];
    const float* ubase = u + (size_t)b * Ln * 3 * Hn + h;
    const float* xbase = x + (size_t)b * Ln * Dn + h;
    float* ybase = y + (size_t)b * Ln * Dn + h;
    int t0 = j * CL;
#pragma unroll 4
    for (int t = t0; t < t0 + CL; ++t) {
        const float* p = ubase + (size_t)t * (3 * Hn);
        float z  = p[0];
        float fp = p[Hn];
        float rp = p[2 * Hn];
        float f = sigmoidf_(fp + bf);
        c = f * c + (1.0f - f) * z;
        float r = sigmoidf_(rp + br);
        float xv = xbase[(size_t)t * Dn];
        ybase[(size_t)t * Dn] = xv + r * c + (1.0f - r) * xv;
    }
}

// ------------------------- LayerNorm (row of 512) ---------------------------
__global__ void __launch_bounds__(128) layernorm_k(
    const float* __restrict__ in, const float* __restrict__ g,
    const float* __restrict__ bb, float* __restrict__ out)
{
    __shared__ float red[4];
    int row = blockIdx.x;
    int tid = threadIdx.x;
    const float4* p = reinterpret_cast<const float4*>(in + (size_t)row * Dn);
    float4 v = p[tid];

    float s = v.x + v.y + v.z + v.w;
#pragma unroll
    for (int o = 16; o; o >>= 1) s += __shfl_xor_sync(0xffffffffu, s, o);
    if ((tid & 31) == 0) red[tid >> 5] = s;
    __syncthreads();
    float mean = (red[0] + red[1] + red[2] + red[3]) * (1.0f / 512.0f);

    float dx = v.x - mean, dy = v.y - mean, dz = v.z - mean, dw = v.w - mean;
    float ss = dx * dx + dy * dy + dz * dz + dw * dw;
#pragma unroll
    for (int o = 16; o; o >>= 1) ss += __shfl_xor_sync(0xffffffffu, ss, o);
    __syncthreads();
    if ((tid & 31) == 0) red[tid >> 5] = ss;
    __syncthreads();
    float var = (red[0] + red[1] + red[2] + red[3]) * (1.0f / 512.0f);
    float rstd = rsqrtf(var + 1e-5f);

    float4 gv = reinterpret_cast<const float4*>(g)[tid];
    float4 bv = reinterpret_cast<const float4*>(bb)[tid];
    float4 o4;
    o4.x = dx * rstd * gv.x + bv.x;
    o4.y = dy * rstd * gv.y + bv.y;
    o4.z = dz * rstd * gv.z + bv.z;
    o4.w = dw * rstd * gv.w + bv.w;
    reinterpret_cast<float4*>(out + (size_t)row * Dn)[tid] = o4;
}

// ------------------------- launch ------------------------------------------
extern "C" void kernel_launch(void* const* d_in, const int* in_sizes, int n_in,
                              void* d_out, int out_size)
{
    const float* x    = (const float*)d_in[0];
    const float* Wsru = (const float*)d_in[1];
    const float* b_f  = (const float*)d_in[2];
    const float* b_r  = (const float*)d_in[3];
    const float* ln1g = (const float*)d_in[4];
    const float* ln1b = (const float*)d_in[5];
    const float* W1   = (const float*)d_in[6];
    const float* b1   = (const float*)d_in[7];
    const float* W2   = (const float*)d_in[8];
    const float* b2   = (const float*)d_in[9];
    const float* ln2g = (const float*)d_in[10];
    const float* ln2b = (const float*)d_in[11];
    float* out = (float*)d_out;

    float *u, *y, *xln, *hb, *P, *A, *cs, *wsruT, *w1T, *w2T;
    cudaGetSymbolAddress((void**)&u,     g_u);
    cudaGetSymbolAddress((void**)&y,     g_y);
    cudaGetSymbolAddress((void**)&xln,   g_xln);
    cudaGetSymbolAddress((void**)&hb,    g_h);
    cudaGetSymbolAddress((void**)&P,     g_P);
    cudaGetSymbolAddress((void**)&A,     g_A);
    cudaGetSymbolAddress((void**)&cs,    g_cs);
    cudaGetSymbolAddress((void**)&wsruT, g_wsruT);
    cudaGetSymbolAddress((void**)&w1T,   g_w1T);
    cudaGetSymbolAddress((void**)&w2T,   g_w2T);

    cudaFuncSetAttribute(gemm_mma<0>, cudaFuncAttributeMaxDynamicSharedMemorySize, SMEM_GEMM);
    cudaFuncSetAttribute(gemm_mma<1>, cudaFuncAttributeMaxDynamicSharedMemorySize, SMEM_GEMM);
    cudaFuncSetAttribute(gemm_mma<2>, cudaFuncAttributeMaxDynamicSharedMemorySize, SMEM_GEMM);

    // 0) transpose weights to [N,K]
    transpose_k<<<dim3(1536 / 32, 512 / 32),  dim3(32, 8)>>>(Wsru, wsruT, 512, 1536);
    transpose_k<<<dim3(2048 / 32, 512 / 32),  dim3(32, 8)>>>(W1,   w1T,   512, 2048);
    transpose_k<<<dim3(512 / 32,  2048 / 32), dim3(32, 8)>>>(W2,   w2T,   2048, 512);

    // 1) u = x @ W_sru
    gemm_mma<0><<<dim3(1536 / BN, M_ROWS / BM), 256, SMEM_GEMM>>>(
        x, wsruT, nullptr, nullptr, u, 1536, 512);

    // 2) SRU chunked scan + highway + residual -> y
    sru_passA<<<BH * NC / 256, 256>>>(u, b_f, P, A);
    sru_combine<<<BH / 256, 256>>>(P, A, cs);
    sru_passC<<<BH * NC / 256, 256>>>(u, x, b_f, b_r, cs, y);

    // 3) LN1 -> xln
    layernorm_k<<<M_ROWS, 128>>>(y, ln1g, ln1b, xln);

    // 4) h = gelu(xln @ W1 + b1)
    gemm_mma<1><<<dim3(2048 / BN, M_ROWS / BM), 256, SMEM_GEMM>>>(
        xln, w1T, b1, nullptr, hb, 2048, 512);

    // 5) y = xln + h @ W2 + b2
    gemm_mma<2><<<dim3(512 / BN, M_ROWS / BM), 256, SMEM_GEMM>>>(
        hb, w2T, b2, xln, y, 512, 2048);

    // 6) LN2 -> out
    layernorm_k<<<M_ROWS, 128>>>(y, ln2g, ln2b, out);
}

// round 4
// speedup vs baseline: 1.6159x; 1.0159x over previous
#include <cuda_runtime.h>
#include <math.h>
#include <cstdint>

// Problem dims (fixed)
constexpr int Bn = 16;
constexpr int Ln = 4096;
constexpr int Dn = 512;
constexpr int Hn = 512;
constexpr int M_ROWS = Bn * Ln;      // 65536
constexpr int NC = 32;               // scan chunks per sequence
constexpr int CL = Ln / NC;          // 128 timesteps per chunk
constexpr int BH = Bn * Hn;          // 8192 channels

// ------------------------- scratch (static device globals) ------------------
__device__ float g_u  [(size_t)M_ROWS * 3 * Hn];
__device__ float g_y  [(size_t)M_ROWS * Dn];
__device__ float g_xln[(size_t)M_ROWS * Dn];
__device__ float g_h  [(size_t)M_ROWS * 4 * Dn];
__device__ float g_P  [BH * NC];
__device__ float g_A  [BH * NC];
__device__ float g_cs [BH * NC];
__device__ float g_wsruT[3 * Hn * Dn];   // [1536,512]
__device__ float g_w1T  [4 * Dn * Dn];   // [2048,512]
__device__ float g_w2T  [Dn * 4 * Dn];   // [512,2048]

__device__ __forceinline__ float sigmoidf_(float t) {
    return 1.0f / (1.0f + __expf(-t));
}
__device__ __forceinline__ float gelu_erf(float v) {
    return 0.5f * v * (1.0f + erff(v * 0.70710678118654752440f));
}

__device__ __forceinline__ uint32_t s2u(const void* p) {
    uint32_t a;
    asm("{ .reg .u64 t; cvta.to.shared.u64 t, %1; cvt.u32.u64 %0, t; }" : "=r"(a) : "l"(p));
    return a;
}
__device__ __forceinline__ void cp16(uint32_t s, const void* g) {
    asm volatile("cp.async.cg.shared.global [%0], [%1], 16;" :: "r"(s), "l"(g));
}

// mma.sync tf32 m16n8k8 (fp32 bits passed through; HW uses tf32 subset)
__device__ __forceinline__ void mma8(float* d, const uint32_t* a, const uint32_t* b) {
    asm volatile(
        "mma.sync.aligned.m16n8k8.row.col.f32.tf32.tf32.f32 "
        "{%0,%1,%2,%3}, {%4,%5,%6,%7}, {%8,%9}, {%0,%1,%2,%3};"
        : "+f"(d[0]), "+f"(d[1]), "+f"(d[2]), "+f"(d[3])
        : "r"(a[0]), "r"(a[1]), "r"(a[2]), "r"(a[3]), "r"(b[0]), "r"(b[1]));
}

// ------------------------- tf32 mma.sync GEMM -------------------------------
// C[M,N] = A[M,K] @ Bt[N,K]^T. BM=128, BN=64, BK=16, NS=4 stage cp.async ring.
// 256 threads = 8 warps (4 m x 2 n), warp tile 32x32. 2 CTAs/SM.
constexpr int BM = 128, BN = 64, BK = 16, NS = 4;
constexpr int ROWS_ST = BM + BN;           // 192 rows per stage (A then B)
constexpr int STGF = ROWS_ST * 20;         // floats per stage (pad 20)
constexpr int SMEM_GEMM = NS * STGF * 4;   // 61440 bytes

__device__ __forceinline__ void load_stage(const float* __restrict__ A,
                                           const float* __restrict__ Bt,
                                           uint32_t sb, int m0, int n0, int K,
                                           int t, int tid) {
    const int buf = t & (NS - 1);
    const float* Ab = A  + (size_t)m0 * K + t * BK;
    const float* Bb = Bt + (size_t)n0 * K + t * BK;
    const uint32_t ss = sb + buf * (STGF * 4);
#pragma unroll
    for (int i = 0; i < 3; i++) {
        int q   = tid + i * 256;   // 0..767
        int row = q >> 2;          // 0..191
        int j   = q & 3;
        uint32_t so = (uint32_t)(row * 20 + j * 4) * 4;
        const float* src = (row < BM) ? (Ab + (size_t)row * K + j * 4)
                                      : (Bb + (size_t)(row - BM) * K + j * 4);
        cp16(ss + so, src);
    }
    asm volatile("cp.async.commit_group;" ::: "memory");
}

// EPI 0: store   EPI 1: gelu(v + bias[n])   EPI 2: v + bias[n] + res[m,n]
template<int EPI>
__global__ void __launch_bounds__(256, 2) gemm_mma(
    const float* __restrict__ A, const float* __restrict__ Bt,
    const float* __restrict__ bias, const float* __restrict__ res,
    float* __restrict__ C, int N, int K)
{
    extern __shared__ float smemf[];
    const uint32_t sb = s2u(smemf);
    const int tid = threadIdx.x;
    const int w   = tid >> 5;
    const int lane = tid & 31;
    const int wm = w & 3;          // 0..3 (32 rows each)
    const int wn = w >> 2;         // 0..1 (32 cols each)
    const int gp = lane >> 2;      // 0..7
    const int tg = lane & 3;       // 0..3
    const int m0 = blockIdx.y * BM;
    const int n0 = blockIdx.x * BN;

    float acc[2][4][4];
#pragma unroll
    for (int i = 0; i < 2; i++)
#pragma unroll
        for (int j = 0; j < 4; j++)
#pragma unroll
            for (int e = 0; e < 4; e++) acc[i][j][e] = 0.0f;

    const int iters = K / BK;

    // prologue: stages 0..NS-2
#pragma unroll
    for (int s = 0; s < NS - 1; s++) load_stage(A, Bt, sb, m0, n0, K, s, tid);

    for (int s = 0; s < iters; s++) {
        const int pend = (iters - 1 - s) < (NS - 2) ? (iters - 1 - s) : (NS - 2);
        if      (pend >= 2) asm volatile("cp.async.wait_group 2;" ::: "memory");
        else if (pend == 1) asm volatile("cp.async.wait_group 1;" ::: "memory");
        else                asm volatile("cp.async.wait_group 0;" ::: "memory");
        __syncthreads();

        if (s + NS - 1 < iters) load_stage(A, Bt, sb, m0, n0, K, s + NS - 1, tid);

        const float* st = smemf + (s & (NS - 1)) * STGF;
        const float* pa = st + (wm * 32 + gp) * 20 + tg;
        const float* pb = st + (BM + wn * 32 + gp) * 20 + tg;

#pragma unroll
        for (int kk = 0; kk < 2; kk++) {
            const int kb = kk * 8;
            uint32_t af[2][4], bf[4][2];
#pragma unroll
            for (int mf = 0; mf < 2; mf++) {
                af[mf][0] = __float_as_uint(pa[mf * 320 + kb]);
                af[mf][1] = __float_as_uint(pa[mf * 320 + 160 + kb]);
                af[mf][2] = __float_as_uint(pa[mf * 320 + kb + 4]);
                af[mf][3] = __float_as_uint(pa[mf * 320 + 160 + kb + 4]);
            }
#pragma unroll
            for (int nf = 0; nf < 4; nf++) {
                bf[nf][0] = __float_as_uint(pb[nf * 160 + kb]);
                bf[nf][1] = __float_as_uint(pb[nf * 160 + kb + 4]);
            }
#pragma unroll
            for (int mf = 0; mf < 2; mf++)
#pragma unroll
                for (int nf = 0; nf < 4; nf++)
                    mma8(acc[mf][nf], af[mf], bf[nf]);
        }
    }

    // epilogue: register accs -> gmem (float2 stores)
#pragma unroll
    for (int mf = 0; mf < 2; mf++) {
        const int ma = m0 + wm * 32 + mf * 16 + gp;
        const int mb = ma + 8;
#pragma unroll
        for (int nf = 0; nf < 4; nf++) {
            const int n = n0 + wn * 32 + nf * 8 + 2 * tg;
            float2 v0 = make_float2(acc[mf][nf][0], acc[mf][nf][1]);
            float2 v1 = make_float2(acc[mf][nf][2], acc[mf][nf][3]);
            if (EPI == 1) {
                float b0 = bias[n], b1 = bias[n + 1];
                v0.x = gelu_erf(v0.x + b0); v0.y = gelu_erf(v0.y + b1);
                v1.x = gelu_erf(v1.x + b0); v1.y = gelu_erf(v1.y + b1);
            } else if (EPI == 2) {
                float b0 = bias[n], b1 = bias[n + 1];
                float2 r0 = *reinterpret_cast<const float2*>(res + (size_t)ma * N + n);
                float2 r1 = *reinterpret_cast<const float2*>(res + (size_t)mb * N + n);
                v0.x += b0 + r0.x; v0.y += b1 + r0.y;
                v1.x += b0 + r1.x; v1.y += b1 + r1.y;
            }
            *reinterpret_cast<float2*>(C + (size_t)ma * N + n) = v0;
            *reinterpret_cast<float2*>(C + (size_t)mb * N + n) = v1;
        }
    }
}

// ------------------------- weight transpose ---------------------------------
__global__ void __launch_bounds__(256) transpose_k(
    const float* __restrict__ in, float* __restrict__ out, int R, int C)
{
    __shared__ float t[32][33];
    int c0 = blockIdx.x * 32, r0 = blockIdx.y * 32;
    int x = threadIdx.x, y0 = threadIdx.y;
#pragma unroll
    for (int i = 0; i < 32; i += 8)
        t[y0 + i][x] = in[(size_t)(r0 + y0 + i) * C + c0 + x];
    __syncthreads();
#pragma unroll
    for (int i = 0; i < 32; i += 8)
        out[(size_t)(c0 + y0 + i) * R + r0 + x] = t[x][y0 + i];
}

// ------------------------- SRU chunked scan ---------------------------------
__global__ void __launch_bounds__(256) sru_passA(
    const float* __restrict__ u, const float* __restrict__ b_f,
    float* __restrict__ Pout, float* __restrict__ Aout)
{
    int idx = blockIdx.x * blockDim.x + threadIdx.x;   // BH*NC threads
    int h = idx % Hn;
    int j = (idx / Hn) % NC;
    int b = idx / (Hn * NC);
    float bf = b_f[h];
    const float* base = u + (size_t)b * Ln * 3 * Hn + h;
    float c = 0.0f, P = 1.0f;
    int t0 = j * CL;
#pragma unroll 4
    for (int t = t0; t < t0 + CL; ++t) {
        const float* p = base + (size_t)t * (3 * Hn);
        float z  = p[0];
        float fp = p[Hn];
        float f  = sigmoidf_(fp + bf);
        c = f * c + (1.0f - f) * z;
        P *= f;
    }
    int ch = b * Hn + h;
    Pout[ch * NC + j] = P;
    Aout[ch * NC + j] = c;
}

__global__ void __launch_bounds__(256) sru_combine(
    const float* __restrict__ P, const float* __restrict__ A,
    float* __restrict__ cstart)
{
    int ch = blockIdx.x * blockDim.x + threadIdx.x;    // BH threads
    float c = 0.0f;
#pragma unroll
    for (int j = 0; j < NC; j++) {
        cstart[ch * NC + j] = c;
        c = P[ch * NC + j] * c + A[ch * NC + j];
    }
}

__global__ void __launch_bounds__(256) sru_passC(
    const float* __restrict__ u, const float* __restrict__ x,
    const float* __restrict__ b_f, const float* __restrict__ b_r,
    const float* __restrict__ cstart, float* __restrict__ y)
{
    int idx = blockIdx.x * blockDim.x + threadIdx.x;
    int h = idx % Hn;
    int j = (idx / Hn) % NC;
    int b = idx / (Hn * NC);
    float bf = b_f[h];
    float br = b_r[h];
    int ch = b * Hn + h;
    float c = cstart[ch * NC + j];
    const float* ubase = u + (size_t)b * Ln * 3 * Hn + h;
    const float* xbase = x + (size_t)b * Ln * Dn + h;
    float* ybase = y + (size_t)b * Ln * Dn + h;
    int t0 = j * CL;
#pragma unroll 4
    for (int t = t0; t < t0 + CL; ++t) {
        const float* p = ubase + (size_t)t * (3 * Hn);
        float z  = p[0];
        float fp = p[Hn];
        float rp = p[2 * Hn];
        float f = sigmoidf_(fp + bf);
        c = f * c + (1.0f - f) * z;
        float r = sigmoidf_(rp + br);
        float xv = xbase[(size_t)t * Dn];
        ybase[(size_t)t * Dn] = xv + r * c + (1.0f - r) * xv;
    }
}

// ------------------------- LayerNorm (row of 512) ---------------------------
__global__ void __launch_bounds__(128) layernorm_k(
    const float* __restrict__ in, const float* __restrict__ g,
    const float* __restrict__ bb, float* __restrict__ out)
{
    __shared__ float red[4];
    int row = blockIdx.x;
    int tid = threadIdx.x;
    const float4* p = reinterpret_cast<const float4*>(in + (size_t)row * Dn);
    float4 v = p[tid];

    float s = v.x + v.y + v.z + v.w;
#pragma unroll
    for (int o = 16; o; o >>= 1) s += __shfl_xor_sync(0xffffffffu, s, o);
    if ((tid & 31) == 0) red[tid >> 5] = s;
    __syncthreads();
    float mean = (red[0] + red[1] + red[2] + red[3]) * (1.0f / 512.0f);

    float dx = v.x - mean, dy = v.y - mean, dz = v.z - mean, dw = v.w - mean;
    float ss = dx * dx + dy * dy + dz * dz + dw * dw;
#pragma unroll
    for (int o = 16; o; o >>= 1) ss += __shfl_xor_sync(0xffffffffu, ss, o);
    __syncthreads();
    if ((tid & 31) == 0) red[tid >> 5] = ss;
    __syncthreads();
    float var = (red[0] + red[1] + red[2] + red[3]) * (1.0f / 512.0f);
    float rstd = rsqrtf(var + 1e-5f);

    float4 gv = reinterpret_cast<const float4*>(g)[tid];
    float4 bv = reinterpret_cast<const float4*>(bb)[tid];
    float4 o4;
    o4.x = dx * rstd * gv.x + bv.x;
    o4.y = dy * rstd * gv.y + bv.y;
    o4.z = dz * rstd * gv.z + bv.z;
    o4.w = dw * rstd * gv.w + bv.w;
    reinterpret_cast<float4*>(out + (size_t)row * Dn)[tid] = o4;
}

// ------------------------- launch ------------------------------------------
extern "C" void kernel_launch(void* const* d_in, const int* in_sizes, int n_in,
                              void* d_out, int out_size)
{
    const float* x    = (const float*)d_in[0];
    const float* Wsru = (const float*)d_in[1];
    const float* b_f  = (const float*)d_in[2];
    const float* b_r  = (const float*)d_in[3];
    const float* ln1g = (const float*)d_in[4];
    const float* ln1b = (const float*)d_in[5];
    const float* W1   = (const float*)d_in[6];
    const float* b1   = (const float*)d_in[7];
    const float* W2   = (const float*)d_in[8];
    const float* b2   = (const float*)d_in[9];
    const float* ln2g = (const float*)d_in[10];
    const float* ln2b = (const float*)d_in[11];
    float* out = (float*)d_out;

    float *u, *y, *xln, *hb, *P, *A, *cs, *wsruT, *w1T, *w2T;
    cudaGetSymbolAddress((void**)&u,     g_u);
    cudaGetSymbolAddress((void**)&y,     g_y);
    cudaGetSymbolAddress((void**)&xln,   g_xln);
    cudaGetSymbolAddress((void**)&hb,    g_h);
    cudaGetSymbolAddress((void**)&P,     g_P);
    cudaGetSymbolAddress((void**)&A,     g_A);
    cudaGetSymbolAddress((void**)&cs,    g_cs);
    cudaGetSymbolAddress((void**)&wsruT, g_wsruT);
    cudaGetSymbolAddress((void**)&w1T,   g_w1T);
    cudaGetSymbolAddress((void**)&w2T,   g_w2T);

    cudaFuncSetAttribute(gemm_mma<0>, cudaFuncAttributeMaxDynamicSharedMemorySize, SMEM_GEMM);
    cudaFuncSetAttribute(gemm_mma<1>, cudaFuncAttributeMaxDynamicSharedMemorySize, SMEM_GEMM);
    cudaFuncSetAttribute(gemm_mma<2>, cudaFuncAttributeMaxDynamicSharedMemorySize, SMEM_GEMM);

    // 0) transpose weights to [N,K]
    transpose_k<<<dim3(1536 / 32, 512 / 32),  dim3(32, 8)>>>(Wsru, wsruT, 512, 1536);
    transpose_k<<<dim3(2048 / 32, 512 / 32),  dim3(32, 8)>>>(W1,   w1T,   512, 2048);
    transpose_k<<<dim3(512 / 32,  2048 / 32), dim3(32, 8)>>>(W2,   w2T,   2048, 512);

    // 1) u = x @ W_sru
    gemm_mma<0><<<dim3(1536 / BN, M_ROWS / BM), 256, SMEM_GEMM>>>(
        x, wsruT, nullptr, nullptr, u, 1536, 512);

    // 2) SRU chunked scan + highway + residual -> y
    sru_passA<<<BH * NC / 256, 256>>>(u, b_f, P, A);
    sru_combine<<<BH / 256, 256>>>(P, A, cs);
    sru_passC<<<BH * NC / 256, 256>>>(u, x, b_f, b_r, cs, y);

    // 3) LN1 -> xln
    layernorm_k<<<M_ROWS, 128>>>(y, ln1g, ln1b, xln);

    // 4) h = gelu(xln @ W1 + b1)
    gemm_mma<1><<<dim3(2048 / BN, M_ROWS / BM), 256, SMEM_GEMM>>>(
        xln, w1T, b1, nullptr, hb, 2048, 512);

    // 5) y = xln + h @ W2 + b2
    gemm_mma<2><<<dim3(512 / BN, M_ROWS / BM), 256, SMEM_GEMM>>>(
        hb, w2T, b2, xln, y, 512, 2048);

    // 6) LN2 -> out
    layernorm_k<<<M_ROWS, 128>>>(y, ln2g, ln2b, out);
}

// round 5
// speedup vs baseline: 2.0888x; 1.2927x over previous
#include <cuda_runtime.h>
#include <math.h>
#include <cstdint>

// Problem dims (fixed)
constexpr int Bn = 16;
constexpr int Ln = 4096;
constexpr int Dn = 512;
constexpr int Hn = 512;
constexpr int M_ROWS = Bn * Ln;      // 65536
constexpr int NC = 32;               // scan chunks per sequence
constexpr int CL = Ln / NC;          // 128 timesteps per chunk
constexpr int BH = Bn * Hn;          // 8192 channels

// ------------------------- scratch (static device globals) ------------------
__device__ float g_u  [(size_t)M_ROWS * 3 * Hn];
__device__ float g_y  [(size_t)M_ROWS * Dn];
__device__ float g_xln[(size_t)M_ROWS * Dn];
__device__ float g_h  [(size_t)M_ROWS * 4 * Dn];
__device__ float g_P  [BH * NC];
__device__ float g_A  [BH * NC];
__device__ float g_cs [BH * NC];
__device__ float g_wsruT[3 * Hn * Dn];   // [1536,512]
__device__ float g_w1T  [4 * Dn * Dn];   // [2048,512]
__device__ float g_w2T  [Dn * 4 * Dn];   // [512,2048]

__device__ __forceinline__ float sigmoidf_(float t) {
    return 1.0f / (1.0f + __expf(-t));
}
__device__ __forceinline__ float gelu_erf(float v) {
    return 0.5f * v * (1.0f + erff(v * 0.70710678118654752440f));
}

__device__ __forceinline__ uint32_t s2u(const void* p) {
    uint32_t a;
    asm("{ .reg .u64 t; cvta.to.shared.u64 t, %1; cvt.u32.u64 %0, t; }" : "=r"(a) : "l"(p));
    return a;
}
__device__ __forceinline__ void cp16(uint32_t s, const void* g) {
    asm volatile("cp.async.cg.shared.global [%0], [%1], 16;" :: "r"(s), "l"(g));
}

// mma.sync tf32 m16n8k8 (fp32 bits passed through; HW uses tf32 subset)
__device__ __forceinline__ void mma8(float* d, const uint32_t* a, const uint32_t* b) {
    asm volatile(
        "mma.sync.aligned.m16n8k8.row.col.f32.tf32.tf32.f32 "
        "{%0,%1,%2,%3}, {%4,%5,%6,%7}, {%8,%9}, {%0,%1,%2,%3};"
        : "+f"(d[0]), "+f"(d[1]), "+f"(d[2]), "+f"(d[3])
        : "r"(a[0]), "r"(a[1]), "r"(a[2]), "r"(a[3]), "r"(b[0]), "r"(b[1]));
}

// ------------------------- tf32 mma.sync GEMM -------------------------------
// C[M,N] = A[M,K] @ Bt[N,K]^T. BM=BN=128, BK=16, NS=4 stage cp.async ring.
// 128 threads = 4 warps (2 m x 2 n), warp tile 64x64. 2 CTAs/SM.
constexpr int BM = 128, BN = 128, BK = 16, NS = 4;
constexpr int ROWS_ST = BM + BN;           // 256 rows per stage (A then B)
constexpr int STGF = ROWS_ST * 20;         // floats per stage (pad 20)
constexpr int SMEM_GEMM = NS * STGF * 4;   // 81920 bytes

__device__ __forceinline__ void load_stage(const float* __restrict__ A,
                                           const float* __restrict__ Bt,
                                           uint32_t sb, int m0, int n0, int K,
                                           int t, int tid) {
    const int buf = t & (NS - 1);
    const float* Ab = A  + (size_t)m0 * K + t * BK;
    const float* Bb = Bt + (size_t)n0 * K + t * BK;
    const uint32_t ss = sb + buf * (STGF * 4);
#pragma unroll
    for (int i = 0; i < 8; i++) {
        int q   = tid + i * 128;   // 0..1023
        int row = q >> 2;          // 0..255
        int j   = q & 3;
        uint32_t so = (uint32_t)(row * 20 + j * 4) * 4;
        const float* src = (row < BM) ? (Ab + (size_t)row * K + j * 4)
                                      : (Bb + (size_t)(row - BM) * K + j * 4);
        cp16(ss + so, src);
    }
    asm volatile("cp.async.commit_group;" ::: "memory");
}

// EPI 0: store   EPI 1: gelu(v + bias[n])   EPI 2: v + bias[n] + res[m,n]
template<int EPI>
__global__ void __launch_bounds__(128, 2) gemm_mma(
    const float* __restrict__ A, const float* __restrict__ Bt,
    const float* __restrict__ bias, const float* __restrict__ res,
    float* __restrict__ C, int N, int K)
{
    extern __shared__ float smemf[];
    const uint32_t sb = s2u(smemf);
    const int tid = threadIdx.x;
    const int w   = tid >> 5;
    const int lane = tid & 31;
    const int wm = w & 1;          // 0..1 (64 rows each)
    const int wn = w >> 1;         // 0..1 (64 cols each)
    const int gp = lane >> 2;      // 0..7
    const int tg = lane & 3;       // 0..3
    const int m0 = blockIdx.y * BM;
    const int n0 = blockIdx.x * BN;

    float acc[4][8][4];
#pragma unroll
    for (int i = 0; i < 4; i++)
#pragma unroll
        for (int j = 0; j < 8; j++)
#pragma unroll
            for (int e = 0; e < 4; e++) acc[i][j][e] = 0.0f;

    const int iters = K / BK;

    // prologue: stages 0..NS-2
#pragma unroll
    for (int s = 0; s < NS - 1; s++) load_stage(A, Bt, sb, m0, n0, K, s, tid);

    for (int s = 0; s < iters; s++) {
        const int pend = (iters - 1 - s) < (NS - 2) ? (iters - 1 - s) : (NS - 2);
        if      (pend >= 2) asm volatile("cp.async.wait_group 2;" ::: "memory");
        else if (pend == 1) asm volatile("cp.async.wait_group 1;" ::: "memory");
        else                asm volatile("cp.async.wait_group 0;" ::: "memory");
        __syncthreads();

        if (s + NS - 1 < iters) load_stage(A, Bt, sb, m0, n0, K, s + NS - 1, tid);

        const float* st = smemf + (s & (NS - 1)) * STGF;
        const float* pa = st + (wm * 64 + gp) * 20 + tg;
        const float* pb = st + (BM + wn * 64 + gp) * 20 + tg;

#pragma unroll
        for (int kk = 0; kk < 2; kk++) {
            const int kb = kk * 8;
            uint32_t af[4][4], bf[8][2];
#pragma unroll
            for (int mf = 0; mf < 4; mf++) {
                af[mf][0] = __float_as_uint(pa[mf * 320 + kb]);
                af[mf][1] = __float_as_uint(pa[mf * 320 + 160 + kb]);
                af[mf][2] = __float_as_uint(pa[mf * 320 + kb + 4]);
                af[mf][3] = __float_as_uint(pa[mf * 320 + 160 + kb + 4]);
            }
#pragma unroll
            for (int nf = 0; nf < 8; nf++) {
                bf[nf][0] = __float_as_uint(pb[nf * 160 + kb]);
                bf[nf][1] = __float_as_uint(pb[nf * 160 + kb + 4]);
            }
#pragma unroll
            for (int mf = 0; mf < 4; mf++)
#pragma unroll
                for (int nf = 0; nf < 8; nf++)
                    mma8(acc[mf][nf], af[mf], bf[nf]);
        }
    }

    // epilogue: register accs -> gmem (float2 stores)
#pragma unroll
    for (int mf = 0; mf < 4; mf++) {
        const int ma = m0 + wm * 64 + mf * 16 + gp;
        const int mb = ma + 8;
#pragma unroll
        for (int nf = 0; nf < 8; nf++) {
            const int n = n0 + wn * 64 + nf * 8 + 2 * tg;
            float2 v0 = make_float2(acc[mf][nf][0], acc[mf][nf][1]);
            float2 v1 = make_float2(acc[mf][nf][2], acc[mf][nf][3]);
            if (EPI == 1) {
                float b0 = bias[n], b1 = bias[n + 1];
                v0.x = gelu_erf(v0.x + b0); v0.y = gelu_erf(v0.y + b1);
                v1.x = gelu_erf(v1.x + b0); v1.y = gelu_erf(v1.y + b1);
            } else if (EPI == 2) {
                float b0 = bias[n], b1 = bias[n + 1];
                float2 r0 = *reinterpret_cast<const float2*>(res + (size_t)ma * N + n);
                float2 r1 = *reinterpret_cast<const float2*>(res + (size_t)mb * N + n);
                v0.x += b0 + r0.x; v0.y += b1 + r0.y;
                v1.x += b0 + r1.x; v1.y += b1 + r1.y;
            }
            *reinterpret_cast<float2*>(C + (size_t)ma * N + n) = v0;
            *reinterpret_cast<float2*>(C + (size_t)mb * N + n) = v1;
        }
    }
}

// ------------------------- weight transpose ---------------------------------
__global__ void __launch_bounds__(256) transpose_k(
    const float* __restrict__ in, float* __restrict__ out, int R, int C)
{
    __shared__ float t[32][33];
    int c0 = blockIdx.x * 32, r0 = blockIdx.y * 32;
    int x = threadIdx.x, y0 = threadIdx.y;
#pragma unroll
    for (int i = 0; i < 32; i += 8)
        t[y0 + i][x] = in[(size_t)(r0 + y0 + i) * C + c0 + x];
    __syncthreads();
#pragma unroll
    for (int i = 0; i < 32; i += 8)
        out[(size_t)(c0 + y0 + i) * R + r0 + x] = t[x][y0 + i];
}

// ------------------------- SRU chunked scan ---------------------------------
__global__ void __launch_bounds__(256) sru_passA(
    const float* __restrict__ u, const float* __restrict__ b_f,
    float* __restrict__ Pout, float* __restrict__ Aout)
{
    int idx = blockIdx.x * blockDim.x + threadIdx.x;   // BH*NC threads
    int h = idx % Hn;
    int j = (idx / Hn) % NC;
    int b = idx / (Hn * NC);
    float bf = b_f[h];
    const float* base = u + (size_t)b * Ln * 3 * Hn + h;
    float c = 0.0f, P = 1.0f;
    int t0 = j * CL;
#pragma unroll 4
    for (int t = t0; t < t0 + CL; ++t) {
        const float* p = base + (size_t)t * (3 * Hn);
        float z  = p[0];
        float fp = p[Hn];
        float f  = sigmoidf_(fp + bf);
        c = f * c + (1.0f - f) * z;
        P *= f;
    }
    int ch = b * Hn + h;
    Pout[ch * NC + j] = P;
    Aout[ch * NC + j] = c;
}

__global__ void __launch_bounds__(256) sru_combine(
    const float* __restrict__ P, const float* __restrict__ A,
    float* __restrict__ cstart)
{
    int ch = blockIdx.x * blockDim.x + threadIdx.x;    // BH threads
    float c = 0.0f;
#pragma unroll
    for (int j = 0; j < NC; j++) {
        cstart[ch * NC + j] = c;
        c = P[ch * NC + j] * c + A[ch * NC + j];
    }
}

__global__ void __launch_bounds__(256) sru_passC(
    const float* __restrict__ u, const float* __restrict__ x,
    const float* __restrict__ b_f, const float* __restrict__ b_r,
    const float* __restrict__ cstart, float* __restrict__ y)
{
    int idx = blockIdx.x * blockDim.x + threadIdx.x;
    int h = idx % Hn;
    int j = (idx / Hn) % NC;
    int b = idx / (Hn * NC);
    float bf = b_f[h];
    float br = b_r[h];
    int ch = b * Hn + h;
    float c = cstart[ch * NC + j];
    const float* ubase = u + (size_t)b * Ln * 3 * Hn + h;
    const float* xbase = x + (size_t)b * Ln * Dn + h;
    float* ybase = y + (size_t)b * Ln * Dn + h;
    int t0 = j * CL;
#pragma unroll 4
    for (int t = t0; t < t0 + CL; ++t) {
        const float* p = ubase + (size_t)t * (3 * Hn);
        float z  = p[0];
        float fp = p[Hn];
        float rp = p[2 * Hn];
        float f = sigmoidf_(fp + bf);
        c = f * c + (1.0f - f) * z;
        float r = sigmoidf_(rp + br);
        float xv = xbase[(size_t)t * Dn];
        ybase[(size_t)t * Dn] = xv + r * c + (1.0f - r) * xv;
    }
}

// ------------------------- LayerNorm (row of 512) ---------------------------
__global__ void __launch_bounds__(128) layernorm_k(
    const float* __restrict__ in, const float* __restrict__ g,
    const float* __restrict__ bb, float* __restrict__ out)
{
    __shared__ float red[4];
    int row = blockIdx.x;
    int tid = threadIdx.x;
    const float4* p = reinterpret_cast<const float4*>(in + (size_t)row * Dn);
    float4 v = p[tid];

    float s = v.x + v.y + v.z + v.w;
#pragma unroll
    for (int o = 16; o; o >>= 1) s += __shfl_xor_sync(0xffffffffu, s, o);
    if ((tid & 31) == 0) red[tid >> 5] = s;
    __syncthreads();
    float mean = (red[0] + red[1] + red[2] + red[3]) * (1.0f / 512.0f);

    float dx = v.x - mean, dy = v.y - mean, dz = v.z - mean, dw = v.w - mean;
    float ss = dx * dx + dy * dy + dz * dz + dw * dw;
#pragma unroll
    for (int o = 16; o; o >>= 1) ss += __shfl_xor_sync(0xffffffffu, ss, o);
    __syncthreads();
    if ((tid & 31) == 0) red[tid >> 5] = ss;
    __syncthreads();
    float var = (red[0] + red[1] + red[2] + red[3]) * (1.0f / 512.0f);
    float rstd = rsqrtf(var + 1e-5f);

    float4 gv = reinterpret_cast<const float4*>(g)[tid];
    float4 bv = reinterpret_cast<const float4*>(bb)[tid];
    float4 o4;
    o4.x = dx * rstd * gv.x + bv.x;
    o4.y = dy * rstd * gv.y + bv.y;
    o4.z = dz * rstd * gv.z + bv.z;
    o4.w = dw * rstd * gv.w + bv.w;
    reinterpret_cast<float4*>(out + (size_t)row * Dn)[tid] = o4;
}

// ------------------------- launch ------------------------------------------
extern "C" void kernel_launch(void* const* d_in, const int* in_sizes, int n_in,
                              void* d_out, int out_size)
{
    const float* x    = (const float*)d_in[0];
    const float* Wsru = (const float*)d_in[1];
    const float* b_f  = (const float*)d_in[2];
    const float* b_r  = (const float*)d_in[3];
    const float* ln1g = (const float*)d_in[4];
    const float* ln1b = (const float*)d_in[5];
    const float* W1   = (const float*)d_in[6];
    const float* b1   = (const float*)d_in[7];
    const float* W2   = (const float*)d_in[8];
    const float* b2   = (const float*)d_in[9];
    const float* ln2g = (const float*)d_in[10];
    const float* ln2b = (const float*)d_in[11];
    float* out = (float*)d_out;

    float *u, *y, *xln, *hb, *P, *A, *cs, *wsruT, *w1T, *w2T;
    cudaGetSymbolAddress((void**)&u,     g_u);
    cudaGetSymbolAddress((void**)&y,     g_y);
    cudaGetSymbolAddress((void**)&xln,   g_xln);
    cudaGetSymbolAddress((void**)&hb,    g_h);
    cudaGetSymbolAddress((void**)&P,     g_P);
    cudaGetSymbolAddress((void**)&A,     g_A);
    cudaGetSymbolAddress((void**)&cs,    g_cs);
    cudaGetSymbolAddress((void**)&wsruT, g_wsruT);
    cudaGetSymbolAddress((void**)&w1T,   g_w1T);
    cudaGetSymbolAddress((void**)&w2T,   g_w2T);

    cudaFuncSetAttribute(gemm_mma<0>, cudaFuncAttributeMaxDynamicSharedMemorySize, SMEM_GEMM);
    cudaFuncSetAttribute(gemm_mma<1>, cudaFuncAttributeMaxDynamicSharedMemorySize, SMEM_GEMM);
    cudaFuncSetAttribute(gemm_mma<2>, cudaFuncAttributeMaxDynamicSharedMemorySize, SMEM_GEMM);

    // 0) transpose weights to [N,K]
    transpose_k<<<dim3(1536 / 32, 512 / 32),  dim3(32, 8)>>>(Wsru, wsruT, 512, 1536);
    transpose_k<<<dim3(2048 / 32, 512 / 32),  dim3(32, 8)>>>(W1,   w1T,   512, 2048);
    transpose_k<<<dim3(512 / 32,  2048 / 32), dim3(32, 8)>>>(W2,   w2T,   2048, 512);

    // 1) u = x @ W_sru
    gemm_mma<0><<<dim3(1536 / BN, M_ROWS / BM), 128, SMEM_GEMM>>>(
        x, wsruT, nullptr, nullptr, u, 1536, 512);

    // 2) SRU chunked scan + highway + residual -> y
    sru_passA<<<BH * NC / 256, 256>>>(u, b_f, P, A);
    sru_combine<<<BH / 256, 256>>>(P, A, cs);
    sru_passC<<<BH * NC / 256, 256>>>(u, x, b_f, b_r, cs, y);

    // 3) LN1 -> xln
    layernorm_k<<<M_ROWS, 128>>>(y, ln1g, ln1b, xln);

    // 4) h = gelu(xln @ W1 + b1)
    gemm_mma<1><<<dim3(2048 / BN, M_ROWS / BM), 128, SMEM_GEMM>>>(
        xln, w1T, b1, nullptr, hb, 2048, 512);

    // 5) y = xln + h @ W2 + b2
    gemm_mma<2><<<dim3(512 / BN, M_ROWS / BM), 128, SMEM_GEMM>>>(
        hb, w2T, b2, xln, y, 512, 2048);

    // 6) LN2 -> out
    layernorm_k<<<M_ROWS, 128>>>(y, ln2g, ln2b, out);
}

// round 6
// speedup vs baseline: 2.1677x; 1.0378x over previous
#include <cuda_runtime.h>
#include <math.h>
#include <cstdint>

// Problem dims (fixed)
constexpr int Bn = 16;
constexpr int Ln = 4096;
constexpr int Dn = 512;
constexpr int Hn = 512;
constexpr int M_ROWS = Bn * Ln;      // 65536
constexpr int NC = 32;               // scan chunks per sequence
constexpr int CL = Ln / NC;          // 128 timesteps per chunk
constexpr int BH = Bn * Hn;          // 8192 channels

// ------------------------- scratch (static device globals) ------------------
__device__ float g_u  [(size_t)M_ROWS * 3 * Hn];
__device__ float g_y  [(size_t)M_ROWS * Dn];
__device__ float g_xln[(size_t)M_ROWS * Dn];
__device__ float g_h  [(size_t)M_ROWS * 4 * Dn];
__device__ float g_P  [BH * NC];
__device__ float g_A  [BH * NC];
__device__ float g_cs [BH * NC];
__device__ float g_wsruT[3 * Hn * Dn];   // [1536,512]
__device__ float g_w1T  [4 * Dn * Dn];   // [2048,512]
__device__ float g_w2T  [Dn * 4 * Dn];   // [512,2048]

__device__ __forceinline__ float sigmoidf_(float t) {
    return 1.0f / (1.0f + __expf(-t));
}
__device__ __forceinline__ float gelu_erf(float v) {
    return 0.5f * v * (1.0f + erff(v * 0.70710678118654752440f));
}

__device__ __forceinline__ uint32_t s2u(const void* p) {
    uint32_t a;
    asm("{ .reg .u64 t; cvta.to.shared.u64 t, %1; cvt.u32.u64 %0, t; }" : "=r"(a) : "l"(p));
    return a;
}
__device__ __forceinline__ void cp16(uint32_t s, const void* g) {
    asm volatile("cp.async.cg.shared.global [%0], [%1], 16;" :: "r"(s), "l"(g));
}

// mma.sync tf32 m16n8k8 (fp32 bits passed through; HW uses tf32 subset)
__device__ __forceinline__ void mma8(float* d,
                                     uint32_t a0, uint32_t a1, uint32_t a2, uint32_t a3,
                                     uint32_t b0, uint32_t b1) {
    asm volatile(
        "mma.sync.aligned.m16n8k8.row.col.f32.tf32.tf32.f32 "
        "{%0,%1,%2,%3}, {%4,%5,%6,%7}, {%8,%9}, {%0,%1,%2,%3};"
        : "+f"(d[0]), "+f"(d[1]), "+f"(d[2]), "+f"(d[3])
        : "r"(a0), "r"(a1), "r"(a2), "r"(a3), "r"(b0), "r"(b1));
}

// ------------------------- tf32 mma.sync GEMM -------------------------------
// C[M,N] = A[M,K] @ Bt[N,K]^T. BM=BN=128, BK=16, NS=4 stage cp.async ring.
// 128 threads = 4 warps (2 m x 2 n), warp tile 64x64. 2 CTAs/SM.
//
// k-slice remap: slice0 of a BK=16 tile = smem positions {4t,4t+1 : t=0..3},
// slice1 = {4t+2,4t+3}. Same map for A and B => dot products pair identical
// logical k. Thread tg's float4 at (row, 4*tg) supplies BOTH slices.
// Stride 16 floats, no pad: float4 phases hit banks {4tg} vs {16+4tg} -> clean.
constexpr int BM = 128, BN = 128, BK = 16, NS = 4;
constexpr int ROWS_ST = BM + BN;           // 256 rows per stage (A then B)
constexpr int STGF = ROWS_ST * BK;         // 4096 floats per stage
constexpr int SMEM_GEMM = NS * STGF * 4;   // 65536 bytes

__device__ __forceinline__ void load_stage(const float* __restrict__ A,
                                           const float* __restrict__ Bt,
                                           uint32_t sb, int m0, int n0, int K,
                                           int t, int tid) {
    const int buf = t & (NS - 1);
    const float* Ab = A  + (size_t)m0 * K + t * BK;
    const float* Bb = Bt + (size_t)n0 * K + t * BK;
    const uint32_t ss = sb + buf * (STGF * 4);
#pragma unroll
    for (int i = 0; i < 8; i++) {
        int q   = tid + i * 128;   // 0..1023 chunks of 16B
        int row = q >> 2;          // 0..255
        int j   = q & 3;
        const float* src = (row < BM) ? (Ab + (size_t)row * K + j * 4)
                                      : (Bb + (size_t)(row - BM) * K + j * 4);
        cp16(ss + (uint32_t)q * 16, src);
    }
    asm volatile("cp.async.commit_group;" ::: "memory");
}

// EPI 0: store   EPI 1: gelu(v + bias[n])   EPI 2: v + bias[n] + res[m,n]
template<int EPI>
__global__ void __launch_bounds__(128, 2) gemm_mma(
    const float* __restrict__ A, const float* __restrict__ Bt,
    const float* __restrict__ bias, const float* __restrict__ res,
    float* __restrict__ C, int N, int K)
{
    extern __shared__ float smemf[];
    const uint32_t sb = s2u(smemf);
    const int tid = threadIdx.x;
    const int w   = tid >> 5;
    const int lane = tid & 31;
    const int wm = w & 1;          // 0..1 (64 rows each)
    const int wn = w >> 1;         // 0..1 (64 cols each)
    const int gp = lane >> 2;      // 0..7
    const int tg = lane & 3;       // 0..3
    const int m0 = blockIdx.y * BM;
    const int n0 = blockIdx.x * BN;

    float acc[4][8][4];
#pragma unroll
    for (int i = 0; i < 4; i++)
#pragma unroll
        for (int j = 0; j < 8; j++)
#pragma unroll
            for (int e = 0; e < 4; e++) acc[i][j][e] = 0.0f;

    const int iters = K / BK;

    // prologue: stages 0..NS-2
#pragma unroll
    for (int s = 0; s < NS - 1; s++) load_stage(A, Bt, sb, m0, n0, K, s, tid);

    for (int s = 0; s < iters; s++) {
        const int pend = (iters - 1 - s) < (NS - 2) ? (iters - 1 - s) : (NS - 2);
        if      (pend >= 2) asm volatile("cp.async.wait_group 2;" ::: "memory");
        else if (pend == 1) asm volatile("cp.async.wait_group 1;" ::: "memory");
        else                asm volatile("cp.async.wait_group 0;" ::: "memory");
        __syncthreads();

        if (s + NS - 1 < iters) load_stage(A, Bt, sb, m0, n0, K, s + NS - 1, tid);

        const float4* st4 = reinterpret_cast<const float4*>(smemf + (s & (NS - 1)) * STGF);
        // float4 index = row*4 + tg   (row stride = 16 floats = 4 float4)
        const float4* pa = st4 + (wm * 64 + gp) * 4 + tg;
        const float4* pb = st4 + (BM + wn * 64 + gp) * 4 + tg;

        float4 alo[4], ahi[4], bv[8];
#pragma unroll
        for (int mf = 0; mf < 4; mf++) {
            alo[mf] = pa[mf * 64];        // rows +16*mf
            ahi[mf] = pa[mf * 64 + 32];   // rows +16*mf+8
        }
#pragma unroll
        for (int nf = 0; nf < 8; nf++)
            bv[nf] = pb[nf * 32];         // rows +8*nf

#pragma unroll
        for (int mf = 0; mf < 4; mf++)
#pragma unroll
            for (int nf = 0; nf < 8; nf++) {
                // slice 0: positions {4t, 4t+1}
                mma8(acc[mf][nf],
                     __float_as_uint(alo[mf].x), __float_as_uint(ahi[mf].x),
                     __float_as_uint(alo[mf].y), __float_as_uint(ahi[mf].y),
                     __float_as_uint(bv[nf].x),  __float_as_uint(bv[nf].y));
                // slice 1: positions {4t+2, 4t+3}
                mma8(acc[mf][nf],
                     __float_as_uint(alo[mf].z), __float_as_uint(ahi[mf].z),
                     __float_as_uint(alo[mf].w), __float_as_uint(ahi[mf].w),
                     __float_as_uint(bv[nf].z),  __float_as_uint(bv[nf].w));
            }
    }

    // epilogue: register accs -> gmem (float2 stores)
#pragma unroll
    for (int mf = 0; mf < 4; mf++) {
        const int ma = m0 + wm * 64 + mf * 16 + gp;
        const int mb = ma + 8;
#pragma unroll
        for (int nf = 0; nf < 8; nf++) {
            const int n = n0 + wn * 64 + nf * 8 + 2 * tg;
            float2 v0 = make_float2(acc[mf][nf][0], acc[mf][nf][1]);
            float2 v1 = make_float2(acc[mf][nf][2], acc[mf][nf][3]);
            if (EPI == 1) {
                float b0 = bias[n], b1 = bias[n + 1];
                v0.x = gelu_erf(v0.x + b0); v0.y = gelu_erf(v0.y + b1);
                v1.x = gelu_erf(v1.x + b0); v1.y = gelu_erf(v1.y + b1);
            } else if (EPI == 2) {
                float b0 = bias[n], b1 = bias[n + 1];
                float2 r0 = *reinterpret_cast<const float2*>(res + (size_t)ma * N + n);
                float2 r1 = *reinterpret_cast<const float2*>(res + (size_t)mb * N + n);
                v0.x += b0 + r0.x; v0.y += b1 + r0.y;
                v1.x += b0 + r1.x; v1.y += b1 + r1.y;
            }
            *reinterpret_cast<float2*>(C + (size_t)ma * N + n) = v0;
            *reinterpret_cast<float2*>(C + (size_t)mb * N + n) = v1;
        }
    }
}

// ------------------------- weight transpose ---------------------------------
__global__ void __launch_bounds__(256) transpose_k(
    const float* __restrict__ in, float* __restrict__ out, int R, int C)
{
    __shared__ float t[32][33];
    int c0 = blockIdx.x * 32, r0 = blockIdx.y * 32;
    int x = threadIdx.x, y0 = threadIdx.y;
#pragma unroll
    for (int i = 0; i < 32; i += 8)
        t[y0 + i][x] = in[(size_t)(r0 + y0 + i) * C + c0 + x];
    __syncthreads();
#pragma unroll
    for (int i = 0; i < 32; i += 8)
        out[(size_t)(c0 + y0 + i) * R + r0 + x] = t[x][y0 + i];
}

// ------------------------- SRU chunked scan ---------------------------------
__global__ void __launch_bounds__(256) sru_passA(
    const float* __restrict__ u, const float* __restrict__ b_f,
    float* __restrict__ Pout, float* __restrict__ Aout)
{
    int idx = blockIdx.x * blockDim.x + threadIdx.x;   // BH*NC threads
    int h = idx % Hn;
    int j = (idx / Hn) % NC;
    int b = idx / (Hn * NC);
    float bf = b_f[h];
    const float* base = u + (size_t)b * Ln * 3 * Hn + h;
    float c = 0.0f, P = 1.0f;
    int t0 = j * CL;
#pragma unroll 4
    for (int t = t0; t < t0 + CL; ++t) {
        const float* p = base + (size_t)t * (3 * Hn);
        float z  = p[0];
        float fp = p[Hn];
        float f  = sigmoidf_(fp + bf);
        c = f * c + (1.0f - f) * z;
        P *= f;
    }
    int ch = b * Hn + h;
    Pout[ch * NC + j] = P;
    Aout[ch * NC + j] = c;
}

__global__ void __launch_bounds__(256) sru_combine(
    const float* __restrict__ P, const float* __restrict__ A,
    float* __restrict__ cstart)
{
    int ch = blockIdx.x * blockDim.x + threadIdx.x;    // BH threads
    float c = 0.0f;
#pragma unroll
    for (int j = 0; j < NC; j++) {
        cstart[ch * NC + j] = c;
        c = P[ch * NC + j] * c + A[ch * NC + j];
    }
}

__global__ void __launch_bounds__(256) sru_passC(
    const float* __restrict__ u, const float* __restrict__ x,
    const float* __restrict__ b_f, const float* __restrict__ b_r,
    const float* __restrict__ cstart, float* __restrict__ y)
{
    int idx = blockIdx.x * blockDim.x + threadIdx.x;
    int h = idx % Hn;
    int j = (idx / Hn) % NC;
    int b = idx / (Hn * NC);
    float bf = b_f[h];
    float br = b_r[h];
    int ch = b * Hn + h;
    float c = cstart[ch * NC + j];
    const float* ubase = u + (size_t)b * Ln * 3 * Hn + h;
    const float* xbase = x + (size_t)b * Ln * Dn + h;
    float* ybase = y + (size_t)b * Ln * Dn + h;
    int t0 = j * CL;
#pragma unroll 4
    for (int t = t0; t < t0 + CL; ++t) {
        const float* p = ubase + (size_t)t * (3 * Hn);
        float z  = p[0];
        float fp = p[Hn];
        float rp = p[2 * Hn];
        float f = sigmoidf_(fp + bf);
        c = f * c + (1.0f - f) * z;
        float r = sigmoidf_(rp + br);
        float xv = xbase[(size_t)t * Dn];
        ybase[(size_t)t * Dn] = xv + r * c + (1.0f - r) * xv;
    }
}

// ------------------------- LayerNorm (row of 512) ---------------------------
__global__ void __launch_bounds__(128) layernorm_k(
    const float* __restrict__ in, const float* __restrict__ g,
    const float* __restrict__ bb, float* __restrict__ out)
{
    __shared__ float red[4];
    int row = blockIdx.x;
    int tid = threadIdx.x;
    const float4* p = reinterpret_cast<const float4*>(in + (size_t)row * Dn);
    float4 v = p[tid];

    float s = v.x + v.y + v.z + v.w;
#pragma unroll
    for (int o = 16; o; o >>= 1) s += __shfl_xor_sync(0xffffffffu, s, o);
    if ((tid & 31) == 0) red[tid >> 5] = s;
    __syncthreads();
    float mean = (red[0] + red[1] + red[2] + red[3]) * (1.0f / 512.0f);

    float dx = v.x - mean, dy = v.y - mean, dz = v.z - mean, dw = v.w - mean;
    float ss = dx * dx + dy * dy + dz * dz + dw * dw;
#pragma unroll
    for (int o = 16; o; o >>= 1) ss += __shfl_xor_sync(0xffffffffu, ss, o);
    __syncthreads();
    if ((tid & 31) == 0) red[tid >> 5] = ss;
    __syncthreads();
    float var = (red[0] + red[1] + red[2] + red[3]) * (1.0f / 512.0f);
    float rstd = rsqrtf(var + 1e-5f);

    float4 gv = reinterpret_cast<const float4*>(g)[tid];
    float4 bv = reinterpret_cast<const float4*>(bb)[tid];
    float4 o4;
    o4.x = dx * rstd * gv.x + bv.x;
    o4.y = dy * rstd * gv.y + bv.y;
    o4.z = dz * rstd * gv.z + bv.z;
    o4.w = dw * rstd * gv.w + bv.w;
    reinterpret_cast<float4*>(out + (size_t)row * Dn)[tid] = o4;
}

// ------------------------- launch ------------------------------------------
extern "C" void kernel_launch(void* const* d_in, const int* in_sizes, int n_in,
                              void* d_out, int out_size)
{
    const float* x    = (const float*)d_in[0];
    const float* Wsru = (const float*)d_in[1];
    const float* b_f  = (const float*)d_in[2];
    const float* b_r  = (const float*)d_in[3];
    const float* ln1g = (const float*)d_in[4];
    const float* ln1b = (const float*)d_in[5];
    const float* W1   = (const float*)d_in[6];
    const float* b1   = (const float*)d_in[7];
    const float* W2   = (const float*)d_in[8];
    const float* b2   = (const float*)d_in[9];
    const float* ln2g = (const float*)d_in[10];
    const float* ln2b = (const float*)d_in[11];
    float* out = (float*)d_out;

    float *u, *y, *xln, *hb, *P, *A, *cs, *wsruT, *w1T, *w2T;
    cudaGetSymbolAddress((void**)&u,     g_u);
    cudaGetSymbolAddress((void**)&y,     g_y);
    cudaGetSymbolAddress((void**)&xln,   g_xln);
    cudaGetSymbolAddress((void**)&hb,    g_h);
    cudaGetSymbolAddress((void**)&P,     g_P);
    cudaGetSymbolAddress((void**)&A,     g_A);
    cudaGetSymbolAddress((void**)&cs,    g_cs);
    cudaGetSymbolAddress((void**)&wsruT, g_wsruT);
    cudaGetSymbolAddress((void**)&w1T,   g_w1T);
    cudaGetSymbolAddress((void**)&w2T,   g_w2T);

    cudaFuncSetAttribute(gemm_mma<0>, cudaFuncAttributeMaxDynamicSharedMemorySize, SMEM_GEMM);
    cudaFuncSetAttribute(gemm_mma<1>, cudaFuncAttributeMaxDynamicSharedMemorySize, SMEM_GEMM);
    cudaFuncSetAttribute(gemm_mma<2>, cudaFuncAttributeMaxDynamicSharedMemorySize, SMEM_GEMM);

    // 0) transpose weights to [N,K]
    transpose_k<<<dim3(1536 / 32, 512 / 32),  dim3(32, 8)>>>(Wsru, wsruT, 512, 1536);
    transpose_k<<<dim3(2048 / 32, 512 / 32),  dim3(32, 8)>>>(W1,   w1T,   512, 2048);
    transpose_k<<<dim3(512 / 32,  2048 / 32), dim3(32, 8)>>>(W2,   w2T,   2048, 512);

    // 1) u = x @ W_sru
    gemm_mma<0><<<dim3(1536 / BN, M_ROWS / BM), 128, SMEM_GEMM>>>(
        x, wsruT, nullptr, nullptr, u, 1536, 512);

    // 2) SRU chunked scan + highway + residual -> y
    sru_passA<<<BH * NC / 256, 256>>>(u, b_f, P, A);
    sru_combine<<<BH / 256, 256>>>(P, A, cs);
    sru_passC<<<BH * NC / 256, 256>>>(u, x, b_f, b_r, cs, y);

    // 3) LN1 -> xln
    layernorm_k<<<M_ROWS, 128>>>(y, ln1g, ln1b, xln);

    // 4) h = gelu(xln @ W1 + b1)
    gemm_mma<1><<<dim3(2048 / BN, M_ROWS / BM), 128, SMEM_GEMM>>>(
        xln, w1T, b1, nullptr, hb, 2048, 512);

    // 5) y = xln + h @ W2 + b2
    gemm_mma<2><<<dim3(512 / BN, M_ROWS / BM), 128, SMEM_GEMM>>>(
        hb, w2T, b2, xln, y, 512, 2048);

    // 6) LN2 -> out
    layernorm_k<<<M_ROWS, 128>>>(y, ln2g, ln2b, out);
}